// round 7
// baseline (speedup 1.0000x reference)
#include <cuda_runtime.h>
#include <stdint.h>

#define B_ 8
#define L_ 2048
#define C_ 256
#define D_ 32
#define NTOK (B_*L_)   // 16384

// -------- scratch (static device arrays: no allocation) --------
__device__ float g_ecg[NTOK*C_];
__device__ float g_pcg[NTOK*C_];
__device__ float g_q[4][NTOK*D_];
__device__ uint32_t g_khb[4][NTOK*(D_/2)];   // K hi, packed bf16x2 along dim
__device__ uint32_t g_klb[4][NTOK*(D_/2)];   // K lo residual
__device__ float g_v[4][NTOK*C_];            // pre-rounded to tf32 grid
__device__ float g_o[2][NTOK*C_];            // intra-attention stash (per half)

// -------- helpers --------
__device__ __forceinline__ uint32_t f2tf(float x) {
    uint32_t u;
    asm("cvt.rna.tf32.f32 %0, %1;" : "=r"(u) : "f"(x));
    return u;
}
__device__ __forceinline__ uint32_t packbf(float lo, float hi) {
    uint32_t r;
    asm("cvt.rn.bf16x2.f32 %0, %1, %2;" : "=r"(r) : "f"(hi), "f"(lo));
    return r;
}
__device__ __forceinline__ float bflo(uint32_t u) { return __uint_as_float(u << 16); }
__device__ __forceinline__ float bfhi(uint32_t u) { return __uint_as_float(u & 0xFFFF0000u); }
__device__ __forceinline__ float trunc_tf(float x) {   // match HW tf32 truncation
    return __uint_as_float(__float_as_uint(x) & 0xFFFFE000u);
}

__device__ __forceinline__ void mma8(float* d, const uint32_t* a,
                                     uint32_t b0, uint32_t b1) {
    asm volatile(
        "mma.sync.aligned.m16n8k8.row.col.f32.tf32.tf32.f32 "
        "{%0,%1,%2,%3}, {%4,%5,%6,%7}, {%8,%9}, {%0,%1,%2,%3};"
        : "+f"(d[0]), "+f"(d[1]), "+f"(d[2]), "+f"(d[3])
        : "r"(a[0]), "r"(a[1]), "r"(a[2]), "r"(a[3]), "r"(b0), "r"(b1));
}
__device__ __forceinline__ void mma16(float* d, const uint32_t* a,
                                      uint32_t b0, uint32_t b1) {
    asm volatile(
        "mma.sync.aligned.m16n8k16.row.col.f32.bf16.bf16.f32 "
        "{%0,%1,%2,%3}, {%4,%5,%6,%7}, {%8,%9}, {%0,%1,%2,%3};"
        : "+f"(d[0]), "+f"(d[1]), "+f"(d[2]), "+f"(d[3])
        : "r"(a[0]), "r"(a[1]), "r"(a[2]), "r"(a[3]), "r"(b0), "r"(b1));
}
__device__ __forceinline__ void cp16(uint32_t dst, const void* src) {
    asm volatile("cp.async.cg.shared.global [%0], [%1], 16;" :: "r"(dst), "l"(src));
}
#define CP_COMMIT() asm volatile("cp.async.commit_group;")
#define CP_WAIT0()  asm volatile("cp.async.wait_group 0;")
#define CP_WAIT1()  asm volatile("cp.async.wait_group 1;")

// -------- split interleaved x[...,2] into two contiguous streams --------
__global__ void split_kernel(const float2* __restrict__ x2, int n) {
    int i = blockIdx.x*blockDim.x + threadIdx.x;
    int stride = gridDim.x*blockDim.x;
    for (; i < n; i += stride) {
        float2 v = x2[i];
        g_ecg[i] = v.x;
        g_pcg[i] = v.y;
    }
}

// ============ 3xTF32 projection GEMMs (raw staging + cp.async) ============
#define PX 36   // 4 mod 32
#define PW 72   // 8 mod 32
#define PROJ_SMEM ((2*128*PX + 2*32*PW)*4)   // 55296 B

struct QKArgs { const float* wa[4]; const float* wb[4]; };
struct VArgs  { const float* wv[4]; };

// ---- fused Q/K pair projection: Q -> f32, K -> pre-split bf16x2 planes ----
__global__ __launch_bounds__(256, 4) void proj_qk(QKArgs args) {
    extern __shared__ float smf[];
    uint32_t sb;
    { uint64_t a = __cvta_generic_to_shared(smf); sb = (uint32_t)a; }
    int t = threadIdx.x;
    int wp = t >> 5, lane = t & 31;
    int g = lane >> 2, t4 = lane & 3;
    int row0 = blockIdx.x * 128;
    int y = blockIdx.y;

    const float* wa = args.wa[y];
    const float* wb = args.wb[y];
    const float* X  = (y < 2) ? g_ecg : g_pcg;
    float* qout = (y==0) ? g_q[0] : (y==1) ? g_q[1] : (y==2) ? g_q[2] : g_q[3];
    int kidx = (y==0) ? 0 : (y==1) ? 3 : (y==2) ? 1 : 2;
    uint32_t* khb = g_khb[kidx];
    uint32_t* klb = g_klb[kidx];
    bool k_is_a = (y == 3);

    #pragma unroll
    for (int i = 0; i < 4; i++) {
        int e = i*256 + t; int r = e >> 3, c4 = e & 7;
        cp16(sb + (r*PX + c4*4)*4, X + (row0 + r)*C_ + c4*4);
    }
    #pragma unroll
    for (int i = 0; i < 2; i++) {
        int e = i*256 + t; int k = e >> 4, c4 = e & 15;
        const float* src = (c4 < 8) ? (wa + k*D_ + c4*4) : (wb + k*D_ + (c4-8)*4);
        cp16(sb + (2*128*PX + k*PW + c4*4)*4, src);
    }
    CP_COMMIT();

    float acc[8][4];
    #pragma unroll
    for (int n = 0; n < 8; n++) { acc[n][0]=acc[n][1]=acc[n][2]=acc[n][3]=0.f; }

    for (int kc = 0; kc < 8; kc++) {
        CP_WAIT0();
        __syncthreads();
        int buf = kc & 1, nbuf = buf ^ 1;
        if (kc < 7) {
            #pragma unroll
            for (int i = 0; i < 4; i++) {
                int e = i*256 + t; int r = e >> 3, c4 = e & 7;
                cp16(sb + (nbuf*128*PX + r*PX + c4*4)*4,
                     X + (row0 + r)*C_ + (kc+1)*32 + c4*4);
            }
            #pragma unroll
            for (int i = 0; i < 2; i++) {
                int e = i*256 + t; int k = e >> 4, c4 = e & 15;
                int krow = (kc+1)*32 + k;
                const float* src = (c4 < 8) ? (wa + krow*D_ + c4*4)
                                            : (wb + krow*D_ + (c4-8)*4);
                cp16(sb + (2*128*PX + nbuf*32*PW + k*PW + c4*4)*4, src);
            }
            CP_COMMIT();
        }
        const float* sX = smf + buf*128*PX;
        const float* sW = smf + 2*128*PX + buf*32*PW;
        #pragma unroll
        for (int kk = 0; kk < 4; kk++) {
            float ar[4];
            ar[0] = sX[(wp*16 + g    )*PX + kk*8 + t4];
            ar[1] = sX[(wp*16 + g + 8)*PX + kk*8 + t4];
            ar[2] = sX[(wp*16 + g    )*PX + kk*8 + t4 + 4];
            ar[3] = sX[(wp*16 + g + 8)*PX + kk*8 + t4 + 4];
            uint32_t ah[4], al[4];
            #pragma unroll
            for (int i = 0; i < 4; i++) {
                ah[i] = f2tf(ar[i]);
                al[i] = __float_as_uint(ar[i] - __uint_as_float(ah[i]));
            }
            #pragma unroll
            for (int n = 0; n < 8; n++) {
                float br0 = sW[(kk*8 + t4    )*PW + n*8 + g];
                float br1 = sW[(kk*8 + t4 + 4)*PW + n*8 + g];
                uint32_t bh0 = f2tf(br0), bh1 = f2tf(br1);
                uint32_t bl0 = __float_as_uint(br0 - __uint_as_float(bh0));
                uint32_t bl1 = __float_as_uint(br1 - __uint_as_float(bh1));
                mma8(acc[n], al, bh0, bh1);
                mma8(acc[n], ah, bl0, bl1);
                mma8(acc[n], ah, bh0, bh1);
            }
        }
    }
    int r0 = row0 + wp*16 + g;
    #pragma unroll
    for (int n = 0; n < 8; n++) {
        bool is_k = k_is_a ? (n < 4) : (n >= 4);
        if (!is_k) {
            int col = (n & 3)*8 + 2*t4;
            *(float2*)&qout[ r0     *D_ + col] = make_float2(acc[n][0], acc[n][1]);
            *(float2*)&qout[(r0 + 8)*D_ + col] = make_float2(acc[n][2], acc[n][3]);
        } else {
            int ci = (n & 3)*4 + t4;
            uint32_t h0 = packbf(acc[n][0], acc[n][1]);
            uint32_t l0 = packbf(acc[n][0] - bflo(h0), acc[n][1] - bfhi(h0));
            uint32_t h1 = packbf(acc[n][2], acc[n][3]);
            uint32_t l1 = packbf(acc[n][2] - bflo(h1), acc[n][3] - bfhi(h1));
            khb[ r0     *16 + ci] = h0;  klb[ r0     *16 + ci] = l0;
            khb[(r0 + 8)*16 + ci] = h1;  klb[(r0 + 8)*16 + ci] = l1;
        }
    }
}

// ---- V projection (output pre-rounded to tf32 grid) ----
__global__ __launch_bounds__(256, 4) void proj_v(VArgs args) {
    extern __shared__ float smf[];
    uint32_t sb;
    { uint64_t a = __cvta_generic_to_shared(smf); sb = (uint32_t)a; }
    int t = threadIdx.x;
    int wp = t >> 5, lane = t & 31;
    int g = lane >> 2, t4 = lane & 3;
    int row0 = blockIdx.x * 128;
    int col0 = blockIdx.y * 64;
    int idx = blockIdx.z;

    const float* wv = args.wv[idx];
    const float* X  = (idx == 0 || idx == 3) ? g_ecg : g_pcg;
    float* out = g_v[idx];

    #pragma unroll
    for (int i = 0; i < 4; i++) {
        int e = i*256 + t; int r = e >> 3, c4 = e & 7;
        cp16(sb + (r*PX + c4*4)*4, X + (row0 + r)*C_ + c4*4);
    }
    #pragma unroll
    for (int i = 0; i < 2; i++) {
        int e = i*256 + t; int k = e >> 4, c4 = e & 15;
        cp16(sb + (2*128*PX + k*PW + c4*4)*4, wv + k*C_ + col0 + c4*4);
    }
    CP_COMMIT();

    float acc[8][4];
    #pragma unroll
    for (int n = 0; n < 8; n++) { acc[n][0]=acc[n][1]=acc[n][2]=acc[n][3]=0.f; }

    for (int kc = 0; kc < 8; kc++) {
        CP_WAIT0();
        __syncthreads();
        int buf = kc & 1, nbuf = buf ^ 1;
        if (kc < 7) {
            #pragma unroll
            for (int i = 0; i < 4; i++) {
                int e = i*256 + t; int r = e >> 3, c4 = e & 7;
                cp16(sb + (nbuf*128*PX + r*PX + c4*4)*4,
                     X + (row0 + r)*C_ + (kc+1)*32 + c4*4);
            }
            #pragma unroll
            for (int i = 0; i < 2; i++) {
                int e = i*256 + t; int k = e >> 4, c4 = e & 15;
                cp16(sb + (2*128*PX + nbuf*32*PW + k*PW + c4*4)*4,
                     wv + ((kc+1)*32 + k)*C_ + col0 + c4*4);
            }
            CP_COMMIT();
        }
        const float* sX = smf + buf*128*PX;
        const float* sW = smf + 2*128*PX + buf*32*PW;
        #pragma unroll
        for (int kk = 0; kk < 4; kk++) {
            float ar[4];
            ar[0] = sX[(wp*16 + g    )*PX + kk*8 + t4];
            ar[1] = sX[(wp*16 + g + 8)*PX + kk*8 + t4];
            ar[2] = sX[(wp*16 + g    )*PX + kk*8 + t4 + 4];
            ar[3] = sX[(wp*16 + g + 8)*PX + kk*8 + t4 + 4];
            uint32_t ah[4], al[4];
            #pragma unroll
            for (int i = 0; i < 4; i++) {
                ah[i] = f2tf(ar[i]);
                al[i] = __float_as_uint(ar[i] - __uint_as_float(ah[i]));
            }
            #pragma unroll
            for (int n = 0; n < 8; n++) {
                float br0 = sW[(kk*8 + t4    )*PW + n*8 + g];
                float br1 = sW[(kk*8 + t4 + 4)*PW + n*8 + g];
                uint32_t bh0 = f2tf(br0), bh1 = f2tf(br1);
                uint32_t bl0 = __float_as_uint(br0 - __uint_as_float(bh0));
                uint32_t bl1 = __float_as_uint(br1 - __uint_as_float(bh1));
                mma8(acc[n], al, bh0, bh1);
                mma8(acc[n], ah, bl0, bl1);
                mma8(acc[n], ah, bh0, bh1);
            }
        }
    }
    int r0 = row0 + wp*16 + g;
    #pragma unroll
    for (int n = 0; n < 8; n++) {
        int col = col0 + n*8 + 2*t4;
        // pre-round to tf32 grid so HW truncation in attention is identity
        *(float2*)&out[ r0     *C_ + col] =
            make_float2(__uint_as_float(f2tf(acc[n][0])), __uint_as_float(f2tf(acc[n][1])));
        *(float2*)&out[(r0 + 8)*C_ + col] =
            make_float2(__uint_as_float(f2tf(acc[n][2])), __uint_as_float(f2tf(acc[n][3])));
    }
}

// ============ attention: 32 rows/CTA, 8 warps (16r x 64c), 3 CTAs/SM ============
#define ROWS 32
#define KT   32
#define VCH  16                 // V half-chunk rows; 3-slot ring
#define NTILES (L_/KT)          // 64
#define PQ   36
#define PKP  20
#define PVA  264
#define PP   36
#define AOFF_KH 0
#define AOFF_KL (AOFF_KH + 2*32*PKP)     // 1280
#define AOFF_V  (AOFF_KL + 2*32*PKP)     // 2560
#define AOFF_P  (AOFF_V + 3*VCH*PVA)     // 15232  (Q staged here too)
#define AOFF_S  (AOFF_P + 32*PP)         // 16384
#define ATTN_U32 (AOFF_S + 128)          // 16512
#define ATTN_SMEM (ATTN_U32*4)           // 66048 B

__global__ __launch_bounds__(256, 3) void attn_mma(float* __restrict__ dst,
        const float* __restrict__ alpha, const float* __restrict__ gamma) {
    extern __shared__ float smf[];
    uint32_t sb;
    { uint64_t a = __cvta_generic_to_shared(smf); sb = (uint32_t)a; }
    const uint32_t* sKh = (const uint32_t*)(smf + AOFF_KH);
    const uint32_t* sKl = (const uint32_t*)(smf + AOFF_KL);
    const uint32_t* sVu = (const uint32_t*)(smf + AOFF_V);
    const float*    sQ  = smf + AOFF_P;      // overlaid: Q dead after hoist
    uint32_t* sPu = (uint32_t*)(smf + AOFF_P);
    float*    sPf = smf + AOFF_P;
    float*    sS  = smf + AOFF_S;

    int t = threadIdx.x;
    int wp = t >> 5, lane = t & 31;
    int g = lane >> 2, t4 = lane & 3;
    int rg = wp >> 2, ch = wp & 3;
    int rb = rg*16;
    int b = blockIdx.y, h = blockIdx.z;
    int row0 = blockIdx.x * ROWS;
    int tokbase = b * L_;

    int idx_a = h ? 2 : 0;
    int idx_b = h ? 3 : 1;
    const float* coefp = h ? gamma : alpha;
    const float SC = 0.17677669529663687f;  // 1/sqrt(32)

    for (int pass = 0; pass < 2; pass++) {
        int idx = (pass == 0) ? idx_a : idx_b;
        const float*    __restrict__ Q  = g_q[idx];
        const uint32_t* __restrict__ KH = g_khb[idx];
        const uint32_t* __restrict__ KL = g_klb[idx];
        const float*    __restrict__ V  = g_v[idx];

        CP_WAIT0();
        __syncthreads();   // drain prior pass; smem free

        // ---- prologue: group A0 = {Q, K tile0, V chunk0}; A1 = {V chunk1} ----
        {
            int r = t >> 3, c4 = t & 7;     // 256 thr = 32x8 f4
            cp16(sb + (AOFF_P + r*PQ + c4*4)*4,
                 Q + (tokbase + row0 + r)*D_ + c4*4);
            int key = (t & 127) >> 2, kc4 = t & 3;
            if (t < 128)
                cp16(sb + (AOFF_KH + key*PKP + kc4*4)*4,
                     KH + (tokbase + key)*16 + kc4*4);
            else
                cp16(sb + (AOFF_KL + key*PKP + kc4*4)*4,
                     KL + (tokbase + key)*16 + kc4*4);
            #pragma unroll
            for (int i = 0; i < 4; i++) {
                int e = i*256 + t; int rv = e >> 6, cv = e & 63;
                cp16(sb + (AOFF_V + rv*PVA + cv*4)*4,
                     V + (tokbase + rv)*C_ + cv*4);
            }
            CP_COMMIT();
            #pragma unroll
            for (int i = 0; i < 4; i++) {
                int e = i*256 + t; int rv = e >> 6, cv = e & 63;
                cp16(sb + (AOFF_V + 1*VCH*PVA + rv*PVA + cv*4)*4,
                     V + (tokbase + VCH + rv)*C_ + cv*4);
            }
            CP_COMMIT();
        }
        CP_WAIT1();
        __syncthreads();   // A0 in: Q, K0, chunk0 ready

        // ---- hoist Q as packed bf16 hi/lo A-fragments ----
        uint32_t qh[2][4], ql[2][4];
        #pragma unroll
        for (int kb = 0; kb < 2; kb++) {
            float2 x0 = *(const float2*)&sQ[(rb + g    )*PQ + kb*16 + 2*t4];
            float2 x1 = *(const float2*)&sQ[(rb + g + 8)*PQ + kb*16 + 2*t4];
            float2 x2 = *(const float2*)&sQ[(rb + g    )*PQ + kb*16 + 2*t4 + 8];
            float2 x3 = *(const float2*)&sQ[(rb + g + 8)*PQ + kb*16 + 2*t4 + 8];
            uint32_t h0 = packbf(x0.x, x0.y), h1 = packbf(x1.x, x1.y);
            uint32_t h2 = packbf(x2.x, x2.y), h3 = packbf(x3.x, x3.y);
            qh[kb][0] = h0; qh[kb][1] = h1; qh[kb][2] = h2; qh[kb][3] = h3;
            ql[kb][0] = packbf(x0.x - bflo(h0), x0.y - bfhi(h0));
            ql[kb][1] = packbf(x1.x - bflo(h1), x1.y - bfhi(h1));
            ql[kb][2] = packbf(x2.x - bflo(h2), x2.y - bfhi(h2));
            ql[kb][3] = packbf(x3.x - bflo(h3), x3.y - bfhi(h3));
        }
        __syncthreads();   // Q region free for P writes

        float acc[8][4];
        #pragma unroll
        for (int n = 0; n < 8; n++)
            acc[n][0]=acc[n][1]=acc[n][2]=acc[n][3]=0.f;
        float lsum0 = 0.f, lsum1 = 0.f;

        for (int kt = 0; kt < NTILES; kt++) {
            // ---- top: K(kt)+chunk(2kt) guaranteed; issue K(kt+1)+chunk(2kt+2) ----
            CP_WAIT1();
            __syncthreads();
            if (kt < NTILES-1) {
                int tok = tokbase + (kt+1)*KT;
                int key = (t & 127) >> 2, kc4 = t & 3;
                int kbuf = ((kt+1) & 1)*32*PKP;
                if (t < 128)
                    cp16(sb + (AOFF_KH + kbuf + key*PKP + kc4*4)*4,
                         KH + (tok + key)*16 + kc4*4);
                else
                    cp16(sb + (AOFF_KL + kbuf + key*PKP + kc4*4)*4,
                         KL + (tok + key)*16 + kc4*4);
                int i2 = 2*kt + 2, sl = i2 % 3, vr = i2*VCH;
                #pragma unroll
                for (int i = 0; i < 4; i++) {
                    int e = i*256 + t; int rv = e >> 6, cv = e & 63;
                    cp16(sb + (AOFF_V + sl*VCH*PVA + rv*PVA + cv*4)*4,
                         V + (tokbase + vr + rv)*C_ + cv*4);
                }
            }
            CP_COMMIT();

            // ---- scores (bf16x3): 16 rows x 8 keys ----
            const uint32_t* sKhb = sKh + (kt & 1)*32*PKP;
            const uint32_t* sKlb = sKl + (kt & 1)*32*PKP;
            float s[4] = {0.f, 0.f, 0.f, 0.f};
            #pragma unroll
            for (int kb = 0; kb < 2; kb++) {
                int krow = (ch*8 + g)*PKP;
                uint32_t bh0 = sKhb[krow + kb*8 + t4];
                uint32_t bh1 = sKhb[krow + kb*8 + t4 + 4];
                uint32_t bl0 = sKlb[krow + kb*8 + t4];
                uint32_t bl1 = sKlb[krow + kb*8 + t4 + 4];
                mma16(s, ql[kb], bh0, bh1);
                mma16(s, qh[kb], bl0, bl1);
                mma16(s, qh[kb], bh0, bh1);
            }
            float p0 = trunc_tf(__expf(s[0]*SC));
            float p1 = trunc_tf(__expf(s[1]*SC));
            float p2 = trunc_tf(__expf(s[2]*SC));
            float p3 = trunc_tf(__expf(s[3]*SC));
            lsum0 += p0 + p1;
            lsum1 += p2 + p3;
            *(float2*)&sPf[(rb + g    )*PP + ch*8 + 2*t4] = make_float2(p0, p1);
            *(float2*)&sPf[(rb + g + 8)*PP + ch*8 + 2*t4] = make_float2(p2, p3);
            __syncthreads();   // P visible

            // ---- P*V kk 0,1 on chunk 2kt (slot (2kt)%3) ----
            {
                const uint32_t* sVa = sVu + ((2*kt) % 3)*VCH*PVA;
                #pragma unroll
                for (int kk = 0; kk < 2; kk++) {
                    uint32_t a[4];
                    a[0] = sPu[(rb + g    )*PP + kk*8 + t4];
                    a[1] = sPu[(rb + g + 8)*PP + kk*8 + t4];
                    a[2] = sPu[(rb + g    )*PP + kk*8 + t4 + 4];
                    a[3] = sPu[(rb + g + 8)*PP + kk*8 + t4 + 4];
                    #pragma unroll
                    for (int n = 0; n < 8; n++) {
                        int col = ch*64 + n*8 + g;
                        uint32_t b0 = sVa[(kk*8 + t4    )*PVA + col];
                        uint32_t b1 = sVa[(kk*8 + t4 + 4)*PVA + col];
                        mma8(acc[n], a, b0, b1);
                    }
                }
            }
            // ---- mid: chunk(2kt+1) guaranteed; chunk-slot of 2kt free ----
            CP_WAIT1();
            __syncthreads();
            if (kt < NTILES-1) {
                int i3 = 2*kt + 3, sl = i3 % 3, vr = i3*VCH;
                #pragma unroll
                for (int i = 0; i < 4; i++) {
                    int e = i*256 + t; int rv = e >> 6, cv = e & 63;
                    cp16(sb + (AOFF_V + sl*VCH*PVA + rv*PVA + cv*4)*4,
                         V + (tokbase + vr + rv)*C_ + cv*4);
                }
            }
            CP_COMMIT();

            // ---- P*V kk 2,3 on chunk 2kt+1 (slot (2kt+1)%3) ----
            {
                const uint32_t* sVb = sVu + ((2*kt + 1) % 3)*VCH*PVA;
                #pragma unroll
                for (int kk = 2; kk < 4; kk++) {
                    uint32_t a[4];
                    a[0] = sPu[(rb + g    )*PP + kk*8 + t4];
                    a[1] = sPu[(rb + g + 8)*PP + kk*8 + t4];
                    a[2] = sPu[(rb + g    )*PP + kk*8 + t4 + 4];
                    a[3] = sPu[(rb + g + 8)*PP + kk*8 + t4 + 4];
                    #pragma unroll
                    for (int n = 0; n < 8; n++) {
                        int col = ch*64 + n*8 + g;
                        uint32_t b0 = sVb[((kk-2)*8 + t4    )*PVA + col];
                        uint32_t b1 = sVb[((kk-2)*8 + t4 + 4)*PVA + col];
                        mma8(acc[n], a, b0, b1);
                    }
                }
            }
            __syncthreads();   // P consumed before next tile overwrites
        }

        // ---- softmax denominators ----
        lsum0 += __shfl_xor_sync(0xffffffffu, lsum0, 1);
        lsum0 += __shfl_xor_sync(0xffffffffu, lsum0, 2);
        lsum1 += __shfl_xor_sync(0xffffffffu, lsum1, 1);
        lsum1 += __shfl_xor_sync(0xffffffffu, lsum1, 2);
        if (t4 == 0) {
            sS[ch*32 + rb + g    ] = lsum0;
            sS[ch*32 + rb + g + 8] = lsum1;
        }
        __syncthreads();
        float d0 = 0.f, d1 = 0.f;
        #pragma unroll
        for (int c = 0; c < 4; c++) {
            d0 += sS[c*32 + rb + g    ];
            d1 += sS[c*32 + rb + g + 8];
        }
        float inv0 = 1.0f / d0;
        float inv1 = 1.0f / d1;

        int r0 = tokbase + row0 + rb + g;
        if (pass == 0) {
            float* st = g_o[h];
            #pragma unroll
            for (int n = 0; n < 8; n++) {
                int col = ch*64 + n*8 + 2*t4;
                *(float2*)&st[ r0     *256 + col] =
                    make_float2(acc[n][0]*inv0, acc[n][1]*inv0);
                *(float2*)&st[(r0 + 8)*256 + col] =
                    make_float2(acc[n][2]*inv1, acc[n][3]*inv1);
            }
        } else {
            float cf = coefp[0];
            const float* st = g_o[h];
            int ooff = h * 256;
            #pragma unroll
            for (int n = 0; n < 8; n++) {
                int col = ch*64 + n*8 + 2*t4;
                float2 s0 = *(const float2*)&st[ r0     *256 + col];
                float2 s1 = *(const float2*)&st[(r0 + 8)*256 + col];
                float2 o0 = make_float2(acc[n][0]*inv0 + cf*s0.x,
                                        acc[n][1]*inv0 + cf*s0.y);
                float2 o1 = make_float2(acc[n][2]*inv1 + cf*s1.x,
                                        acc[n][3]*inv1 + cf*s1.y);
                *(float2*)&dst[ r0     *512 + ooff + col] = o0;
                *(float2*)&dst[(r0 + 8)*512 + ooff + col] = o1;
            }
        }
        __syncthreads();   // sS/output done before next pass restages
    }
}

extern "C" void kernel_launch(void* const* d_in, const int* in_sizes, int n_in,
                              void* d_out, int out_size) {
    const float* x = (const float*)d_in[0];
    const float* wt[12];
    for (int i = 0; i < 12; i++) wt[i] = (const float*)d_in[1+i];
    const float* alpha = (const float*)d_in[13];
    const float* gamma = (const float*)d_in[14];
    float* out = (float*)d_out;

    cudaFuncSetAttribute(proj_qk,
                         cudaFuncAttributeMaxDynamicSharedMemorySize, PROJ_SMEM);
    cudaFuncSetAttribute(proj_v,
                         cudaFuncAttributeMaxDynamicSharedMemorySize, PROJ_SMEM);
    cudaFuncSetAttribute(attn_mma,
                         cudaFuncAttributeMaxDynamicSharedMemorySize, ATTN_SMEM);

    split_kernel<<<2048, 256>>>((const float2*)x, NTOK*C_);

    // y0: X=ecg  wa=w1->q0   wb=w2->k0
    // y1: X=ecg  wa=w4->q1   wb=w11->k3
    // y2: X=pcg  wa=w7->q2   wb=w5->k1
    // y3: X=pcg  wa=w8->k2   wb=w10->q3
    QKArgs qk;
    qk.wa[0] = wt[0];  qk.wb[0] = wt[1];
    qk.wa[1] = wt[3];  qk.wb[1] = wt[10];
    qk.wa[2] = wt[6];  qk.wb[2] = wt[4];
    qk.wa[3] = wt[7];  qk.wb[3] = wt[9];
    proj_qk<<<dim3(NTOK/128, 4), 256, PROJ_SMEM>>>(qk);

    VArgs va;
    va.wv[0] = wt[2]; va.wv[1] = wt[5]; va.wv[2] = wt[8]; va.wv[3] = wt[11];
    proj_v<<<dim3(NTOK/128, 4, 4), 256, PROJ_SMEM>>>(va);

    dim3 ag(L_/ROWS, B_, 2);
    attn_mma<<<ag, 256, ATTN_SMEM>>>(out, alpha, gamma);
}

// round 8
// speedup vs baseline: 1.3610x; 1.3610x over previous
#include <cuda_runtime.h>
#include <stdint.h>

#define B_ 8
#define L_ 2048
#define C_ 256
#define D_ 32
#define NTOK (B_*L_)   // 16384

// -------- scratch (static device arrays: no allocation) --------
__device__ float g_ecg[NTOK*C_];
__device__ float g_pcg[NTOK*C_];
__device__ float g_q[4][NTOK*D_];
__device__ uint32_t g_khb[4][NTOK*(D_/2)];   // K hi, packed bf16x2 along dim
__device__ uint32_t g_klb[4][NTOK*(D_/2)];   // K lo residual
__device__ float g_v[4][NTOK*C_];            // pre-rounded to tf32 grid
__device__ float g_o[2][NTOK*C_];            // intra-attention stash (per half)

// -------- helpers --------
__device__ __forceinline__ uint32_t f2tf(float x) {
    uint32_t u;
    asm("cvt.rna.tf32.f32 %0, %1;" : "=r"(u) : "f"(x));
    return u;
}
__device__ __forceinline__ uint32_t packbf(float lo, float hi) {
    uint32_t r;
    asm("cvt.rn.bf16x2.f32 %0, %1, %2;" : "=r"(r) : "f"(hi), "f"(lo));
    return r;
}
__device__ __forceinline__ float bflo(uint32_t u) { return __uint_as_float(u << 16); }
__device__ __forceinline__ float bfhi(uint32_t u) { return __uint_as_float(u & 0xFFFF0000u); }
__device__ __forceinline__ float trunc_tf(float x) {   // match HW tf32 truncation
    return __uint_as_float(__float_as_uint(x) & 0xFFFFE000u);
}

__device__ __forceinline__ void mma8(float* d, const uint32_t* a,
                                     uint32_t b0, uint32_t b1) {
    asm volatile(
        "mma.sync.aligned.m16n8k8.row.col.f32.tf32.tf32.f32 "
        "{%0,%1,%2,%3}, {%4,%5,%6,%7}, {%8,%9}, {%0,%1,%2,%3};"
        : "+f"(d[0]), "+f"(d[1]), "+f"(d[2]), "+f"(d[3])
        : "r"(a[0]), "r"(a[1]), "r"(a[2]), "r"(a[3]), "r"(b0), "r"(b1));
}
__device__ __forceinline__ void mma16(float* d, const uint32_t* a,
                                      uint32_t b0, uint32_t b1) {
    asm volatile(
        "mma.sync.aligned.m16n8k16.row.col.f32.bf16.bf16.f32 "
        "{%0,%1,%2,%3}, {%4,%5,%6,%7}, {%8,%9}, {%0,%1,%2,%3};"
        : "+f"(d[0]), "+f"(d[1]), "+f"(d[2]), "+f"(d[3])
        : "r"(a[0]), "r"(a[1]), "r"(a[2]), "r"(a[3]), "r"(b0), "r"(b1));
}
__device__ __forceinline__ void cp16(uint32_t dst, const void* src) {
    asm volatile("cp.async.cg.shared.global [%0], [%1], 16;" :: "r"(dst), "l"(src));
}
#define CP_COMMIT() asm volatile("cp.async.commit_group;")
#define CP_WAIT0()  asm volatile("cp.async.wait_group 0;")

// -------- split interleaved x[...,2] into two contiguous streams --------
__global__ void split_kernel(const float2* __restrict__ x2, int n) {
    int i = blockIdx.x*blockDim.x + threadIdx.x;
    int stride = gridDim.x*blockDim.x;
    for (; i < n; i += stride) {
        float2 v = x2[i];
        g_ecg[i] = v.x;
        g_pcg[i] = v.y;
    }
}

// ============ single-tf32 projection GEMMs (rna operands; outputs re-rounded downstream) ============
#define PX 36   // 4 mod 32
#define PW 72   // 8 mod 32
#define PROJ_SMEM ((2*128*PX + 2*32*PW)*4)   // 55296 B

struct QKArgs { const float* wa[4]; const float* wb[4]; };
struct VArgs  { const float* wv[4]; };

// ---- fused Q/K pair projection: Q -> f32, K -> pre-split bf16x2 planes ----
__global__ __launch_bounds__(256, 4) void proj_qk(QKArgs args) {
    extern __shared__ float smf[];
    uint32_t sb;
    { uint64_t a = __cvta_generic_to_shared(smf); sb = (uint32_t)a; }
    int t = threadIdx.x;
    int wp = t >> 5, lane = t & 31;
    int g = lane >> 2, t4 = lane & 3;
    int row0 = blockIdx.x * 128;
    int y = blockIdx.y;

    const float* wa = args.wa[y];
    const float* wb = args.wb[y];
    const float* X  = (y < 2) ? g_ecg : g_pcg;
    float* qout = (y==0) ? g_q[0] : (y==1) ? g_q[1] : (y==2) ? g_q[2] : g_q[3];
    int kidx = (y==0) ? 0 : (y==1) ? 3 : (y==2) ? 1 : 2;
    uint32_t* khb = g_khb[kidx];
    uint32_t* klb = g_klb[kidx];
    bool k_is_a = (y == 3);

    #pragma unroll
    for (int i = 0; i < 4; i++) {
        int e = i*256 + t; int r = e >> 3, c4 = e & 7;
        cp16(sb + (r*PX + c4*4)*4, X + (row0 + r)*C_ + c4*4);
    }
    #pragma unroll
    for (int i = 0; i < 2; i++) {
        int e = i*256 + t; int k = e >> 4, c4 = e & 15;
        const float* src = (c4 < 8) ? (wa + k*D_ + c4*4) : (wb + k*D_ + (c4-8)*4);
        cp16(sb + (2*128*PX + k*PW + c4*4)*4, src);
    }
    CP_COMMIT();

    float acc[8][4];
    #pragma unroll
    for (int n = 0; n < 8; n++) { acc[n][0]=acc[n][1]=acc[n][2]=acc[n][3]=0.f; }

    for (int kc = 0; kc < 8; kc++) {
        CP_WAIT0();
        __syncthreads();
        int buf = kc & 1, nbuf = buf ^ 1;
        if (kc < 7) {
            #pragma unroll
            for (int i = 0; i < 4; i++) {
                int e = i*256 + t; int r = e >> 3, c4 = e & 7;
                cp16(sb + (nbuf*128*PX + r*PX + c4*4)*4,
                     X + (row0 + r)*C_ + (kc+1)*32 + c4*4);
            }
            #pragma unroll
            for (int i = 0; i < 2; i++) {
                int e = i*256 + t; int k = e >> 4, c4 = e & 15;
                int krow = (kc+1)*32 + k;
                const float* src = (c4 < 8) ? (wa + krow*D_ + c4*4)
                                            : (wb + krow*D_ + (c4-8)*4);
                cp16(sb + (2*128*PX + nbuf*32*PW + k*PW + c4*4)*4, src);
            }
            CP_COMMIT();
        }
        const float* sX = smf + buf*128*PX;
        const float* sW = smf + 2*128*PX + buf*32*PW;
        #pragma unroll
        for (int kk = 0; kk < 4; kk++) {
            uint32_t ah[4];
            ah[0] = f2tf(sX[(wp*16 + g    )*PX + kk*8 + t4]);
            ah[1] = f2tf(sX[(wp*16 + g + 8)*PX + kk*8 + t4]);
            ah[2] = f2tf(sX[(wp*16 + g    )*PX + kk*8 + t4 + 4]);
            ah[3] = f2tf(sX[(wp*16 + g + 8)*PX + kk*8 + t4 + 4]);
            #pragma unroll
            for (int n = 0; n < 8; n++) {
                uint32_t bh0 = f2tf(sW[(kk*8 + t4    )*PW + n*8 + g]);
                uint32_t bh1 = f2tf(sW[(kk*8 + t4 + 4)*PW + n*8 + g]);
                mma8(acc[n], ah, bh0, bh1);
            }
        }
    }
    int r0 = row0 + wp*16 + g;
    #pragma unroll
    for (int n = 0; n < 8; n++) {
        bool is_k = k_is_a ? (n < 4) : (n >= 4);
        if (!is_k) {
            int col = (n & 3)*8 + 2*t4;
            *(float2*)&qout[ r0     *D_ + col] = make_float2(acc[n][0], acc[n][1]);
            *(float2*)&qout[(r0 + 8)*D_ + col] = make_float2(acc[n][2], acc[n][3]);
        } else {
            int ci = (n & 3)*4 + t4;
            uint32_t h0 = packbf(acc[n][0], acc[n][1]);
            uint32_t l0 = packbf(acc[n][0] - bflo(h0), acc[n][1] - bfhi(h0));
            uint32_t h1 = packbf(acc[n][2], acc[n][3]);
            uint32_t l1 = packbf(acc[n][2] - bflo(h1), acc[n][3] - bfhi(h1));
            khb[ r0     *16 + ci] = h0;  klb[ r0     *16 + ci] = l0;
            khb[(r0 + 8)*16 + ci] = h1;  klb[(r0 + 8)*16 + ci] = l1;
        }
    }
}

// ---- V projection (output pre-rounded to tf32 grid) ----
__global__ __launch_bounds__(256, 4) void proj_v(VArgs args) {
    extern __shared__ float smf[];
    uint32_t sb;
    { uint64_t a = __cvta_generic_to_shared(smf); sb = (uint32_t)a; }
    int t = threadIdx.x;
    int wp = t >> 5, lane = t & 31;
    int g = lane >> 2, t4 = lane & 3;
    int row0 = blockIdx.x * 128;
    int col0 = blockIdx.y * 64;
    int idx = blockIdx.z;

    const float* wv = args.wv[idx];
    const float* X  = (idx == 0 || idx == 3) ? g_ecg : g_pcg;
    float* out = g_v[idx];

    #pragma unroll
    for (int i = 0; i < 4; i++) {
        int e = i*256 + t; int r = e >> 3, c4 = e & 7;
        cp16(sb + (r*PX + c4*4)*4, X + (row0 + r)*C_ + c4*4);
    }
    #pragma unroll
    for (int i = 0; i < 2; i++) {
        int e = i*256 + t; int k = e >> 4, c4 = e & 15;
        cp16(sb + (2*128*PX + k*PW + c4*4)*4, wv + k*C_ + col0 + c4*4);
    }
    CP_COMMIT();

    float acc[8][4];
    #pragma unroll
    for (int n = 0; n < 8; n++) { acc[n][0]=acc[n][1]=acc[n][2]=acc[n][3]=0.f; }

    for (int kc = 0; kc < 8; kc++) {
        CP_WAIT0();
        __syncthreads();
        int buf = kc & 1, nbuf = buf ^ 1;
        if (kc < 7) {
            #pragma unroll
            for (int i = 0; i < 4; i++) {
                int e = i*256 + t; int r = e >> 3, c4 = e & 7;
                cp16(sb + (nbuf*128*PX + r*PX + c4*4)*4,
                     X + (row0 + r)*C_ + (kc+1)*32 + c4*4);
            }
            #pragma unroll
            for (int i = 0; i < 2; i++) {
                int e = i*256 + t; int k = e >> 4, c4 = e & 15;
                cp16(sb + (2*128*PX + nbuf*32*PW + k*PW + c4*4)*4,
                     wv + ((kc+1)*32 + k)*C_ + col0 + c4*4);
            }
            CP_COMMIT();
        }
        const float* sX = smf + buf*128*PX;
        const float* sW = smf + 2*128*PX + buf*32*PW;
        #pragma unroll
        for (int kk = 0; kk < 4; kk++) {
            uint32_t ah[4];
            ah[0] = f2tf(sX[(wp*16 + g    )*PX + kk*8 + t4]);
            ah[1] = f2tf(sX[(wp*16 + g + 8)*PX + kk*8 + t4]);
            ah[2] = f2tf(sX[(wp*16 + g    )*PX + kk*8 + t4 + 4]);
            ah[3] = f2tf(sX[(wp*16 + g + 8)*PX + kk*8 + t4 + 4]);
            #pragma unroll
            for (int n = 0; n < 8; n++) {
                uint32_t bh0 = f2tf(sW[(kk*8 + t4    )*PW + n*8 + g]);
                uint32_t bh1 = f2tf(sW[(kk*8 + t4 + 4)*PW + n*8 + g]);
                mma8(acc[n], ah, bh0, bh1);
            }
        }
    }
    int r0 = row0 + wp*16 + g;
    #pragma unroll
    for (int n = 0; n < 8; n++) {
        int col = col0 + n*8 + 2*t4;
        // pre-round to tf32 grid so HW truncation in attention is identity
        *(float2*)&out[ r0     *C_ + col] =
            make_float2(__uint_as_float(f2tf(acc[n][0])), __uint_as_float(f2tf(acc[n][1])));
        *(float2*)&out[(r0 + 8)*C_ + col] =
            make_float2(__uint_as_float(f2tf(acc[n][2])), __uint_as_float(f2tf(acc[n][3])));
    }
}

// ============ attention (R6 structure): 64 rows/CTA, 8 warps = 32r x 64c, 2 CTAs/SM ============
#define ROWS 64
#define KT   32
#define PQ   36
#define PKP  20     // packed K plane row stride (u32)
#define PVA  264
#define PP   36
#define AOFF_Q  0
#define AOFF_KH (AOFF_Q  + 64*PQ)           // 2304
#define AOFF_KL (AOFF_KH + 2*32*PKP)        // 3584
#define AOFF_V  (AOFF_KL + 2*32*PKP)        // 4864
#define AOFF_P  (AOFF_V  + 2*32*PVA)        // 21760
#define AOFF_S  (AOFF_P  + 64*PP)           // 24064
#define ATTN_U32 (AOFF_S + 256)             // 24320
#define ATTN_SMEM (ATTN_U32*4)              // 97280 B

__global__ __launch_bounds__(256, 2) void attn_mma(float* __restrict__ dst,
        const float* __restrict__ alpha, const float* __restrict__ gamma) {
    extern __shared__ float smf[];
    uint32_t sb;
    { uint64_t a = __cvta_generic_to_shared(smf); sb = (uint32_t)a; }
    const float*    sQ  = smf + AOFF_Q;
    const uint32_t* sKh = (const uint32_t*)(smf + AOFF_KH);
    const uint32_t* sKl = (const uint32_t*)(smf + AOFF_KL);
    const uint32_t* sVu = (const uint32_t*)(smf + AOFF_V);
    uint32_t* sPu = (uint32_t*)(smf + AOFF_P);
    float*    sPf = smf + AOFF_P;
    float*    sS  = smf + AOFF_S;

    int t = threadIdx.x;
    int wp = t >> 5, lane = t & 31;
    int g = lane >> 2, t4 = lane & 3;
    int rg = wp >> 2, ch = wp & 3;
    int b = blockIdx.y, h = blockIdx.z;
    int row0 = blockIdx.x * ROWS;
    int tokbase = b * L_;

    int idx_a = h ? 2 : 0;
    int idx_b = h ? 3 : 1;
    const float* coefp = h ? gamma : alpha;
    const float SC = 0.17677669529663687f;  // 1/sqrt(32)

    for (int pass = 0; pass < 2; pass++) {
        int idx = (pass == 0) ? idx_a : idx_b;
        const float*    __restrict__ Q  = g_q[idx];
        const uint32_t* __restrict__ KH = g_khb[idx];
        const uint32_t* __restrict__ KL = g_klb[idx];
        const float*    __restrict__ V  = g_v[idx];

        __syncthreads();
        // ---- prologue: stage Q + tile 0 (K planes, V) ----
        {
            #pragma unroll
            for (int i = 0; i < 2; i++) {
                int e = i*256 + t; int r = e >> 3, c4 = e & 7;
                cp16(sb + (AOFF_Q + r*PQ + c4*4)*4,
                     Q + (tokbase + row0 + r)*D_ + c4*4);
            }
            {
                int key = (t & 127) >> 2, c4 = t & 3;
                if (t < 128)
                    cp16(sb + (AOFF_KH + key*PKP + c4*4)*4,
                         KH + (tokbase + key)*16 + c4*4);
                else
                    cp16(sb + (AOFF_KL + key*PKP + c4*4)*4,
                         KL + (tokbase + key)*16 + c4*4);
            }
            #pragma unroll
            for (int i = 0; i < 8; i++) {
                int e = i*256 + t; int rv = e >> 6, cv = e & 63;
                cp16(sb + (AOFF_V + rv*PVA + cv*4)*4,
                     V + (tokbase + rv)*C_ + cv*4);
            }
            CP_COMMIT();
        }
        CP_WAIT0();
        __syncthreads();

        // ---- hoist Q as packed bf16 hi/lo A-fragments (whole pass) ----
        uint32_t qh[2][2][4], ql[2][2][4];
        #pragma unroll
        for (int mt = 0; mt < 2; mt++) {
            int rb = rg*32 + mt*16;
            #pragma unroll
            for (int kb = 0; kb < 2; kb++) {
                float2 x0 = *(const float2*)&sQ[(rb + g    )*PQ + kb*16 + 2*t4];
                float2 x1 = *(const float2*)&sQ[(rb + g + 8)*PQ + kb*16 + 2*t4];
                float2 x2 = *(const float2*)&sQ[(rb + g    )*PQ + kb*16 + 2*t4 + 8];
                float2 x3 = *(const float2*)&sQ[(rb + g + 8)*PQ + kb*16 + 2*t4 + 8];
                uint32_t h0 = packbf(x0.x, x0.y), h1 = packbf(x1.x, x1.y);
                uint32_t h2 = packbf(x2.x, x2.y), h3 = packbf(x3.x, x3.y);
                qh[mt][kb][0] = h0; qh[mt][kb][1] = h1;
                qh[mt][kb][2] = h2; qh[mt][kb][3] = h3;
                ql[mt][kb][0] = packbf(x0.x - bflo(h0), x0.y - bfhi(h0));
                ql[mt][kb][1] = packbf(x1.x - bflo(h1), x1.y - bfhi(h1));
                ql[mt][kb][2] = packbf(x2.x - bflo(h2), x2.y - bfhi(h2));
                ql[mt][kb][3] = packbf(x3.x - bflo(h3), x3.y - bfhi(h3));
            }
        }

        float acc[2][8][4];
        #pragma unroll
        for (int mt = 0; mt < 2; mt++)
            #pragma unroll
            for (int n = 0; n < 8; n++)
                acc[mt][n][0]=acc[mt][n][1]=acc[mt][n][2]=acc[mt][n][3]=0.f;
        float lsum[2][2] = {{0.f,0.f},{0.f,0.f}};

        for (int kt = 0; kt < L_/KT; kt++) {
            int buf = kt & 1, nbuf = buf ^ 1;
            if (kt < L_/KT - 1) {
                int tok = tokbase + (kt+1)*KT;
                {
                    int key = (t & 127) >> 2, c4 = t & 3;
                    if (t < 128)
                        cp16(sb + (AOFF_KH + nbuf*32*PKP + key*PKP + c4*4)*4,
                             KH + (tok + key)*16 + c4*4);
                    else
                        cp16(sb + (AOFF_KL + nbuf*32*PKP + key*PKP + c4*4)*4,
                             KL + (tok + key)*16 + c4*4);
                }
                #pragma unroll
                for (int i = 0; i < 8; i++) {
                    int e = i*256 + t; int rv = e >> 6, cv = e & 63;
                    cp16(sb + (AOFF_V + nbuf*32*PVA + rv*PVA + cv*4)*4,
                         V + (tok + rv)*C_ + cv*4);
                }
                CP_COMMIT();
            }
            const uint32_t* sKhb = sKh + buf*32*PKP;
            const uint32_t* sKlb = sKl + buf*32*PKP;
            const uint32_t* sVb  = sVu + buf*32*PVA;

            // ---- scores (bf16x3, k16): 2 m-tiles x 8 keys ----
            float s[2][4];
            s[0][0]=s[0][1]=s[0][2]=s[0][3]=0.f;
            s[1][0]=s[1][1]=s[1][2]=s[1][3]=0.f;
            #pragma unroll
            for (int kb = 0; kb < 2; kb++) {
                int krow = (ch*8 + g)*PKP;
                uint32_t bh0 = sKhb[krow + kb*8 + t4];
                uint32_t bh1 = sKhb[krow + kb*8 + t4 + 4];
                uint32_t bl0 = sKlb[krow + kb*8 + t4];
                uint32_t bl1 = sKlb[krow + kb*8 + t4 + 4];
                mma16(s[0], ql[0][kb], bh0, bh1);
                mma16(s[0], qh[0][kb], bl0, bl1);
                mma16(s[0], qh[0][kb], bh0, bh1);
                mma16(s[1], ql[1][kb], bh0, bh1);
                mma16(s[1], qh[1][kb], bl0, bl1);
                mma16(s[1], qh[1][kb], bh0, bh1);
            }
            #pragma unroll
            for (int mt = 0; mt < 2; mt++) {
                int rb = rg*32 + mt*16;
                float p0 = trunc_tf(__expf(s[mt][0]*SC));
                float p1 = trunc_tf(__expf(s[mt][1]*SC));
                float p2 = trunc_tf(__expf(s[mt][2]*SC));
                float p3 = trunc_tf(__expf(s[mt][3]*SC));
                lsum[mt][0] += p0 + p1;
                lsum[mt][1] += p2 + p3;
                *(float2*)&sPf[(rb + g    )*PP + ch*8 + 2*t4] = make_float2(p0, p1);
                *(float2*)&sPf[(rb + g + 8)*PP + ch*8 + 2*t4] = make_float2(p2, p3);
            }
            __syncthreads();

            // ---- P*V (tf32, truncation-exact): 2 m-tiles x 64 cols ----
            #pragma unroll
            for (int kk = 0; kk < 4; kk++) {
                uint32_t a[2][4];
                #pragma unroll
                for (int mt = 0; mt < 2; mt++) {
                    int rb = rg*32 + mt*16;
                    a[mt][0] = sPu[(rb + g    )*PP + kk*8 + t4];
                    a[mt][1] = sPu[(rb + g + 8)*PP + kk*8 + t4];
                    a[mt][2] = sPu[(rb + g    )*PP + kk*8 + t4 + 4];
                    a[mt][3] = sPu[(rb + g + 8)*PP + kk*8 + t4 + 4];
                }
                #pragma unroll
                for (int n = 0; n < 8; n++) {
                    int col = ch*64 + n*8 + g;
                    uint32_t b0 = sVb[(kk*8 + t4    )*PVA + col];
                    uint32_t b1 = sVb[(kk*8 + t4 + 4)*PVA + col];
                    mma8(acc[0][n], a[0], b0, b1);
                    mma8(acc[1][n], a[1], b0, b1);
                }
            }
            if (kt < L_/KT - 1) {
                CP_WAIT0();
            }
            __syncthreads();   // next K/V ready AND sP consumed before rewrite
        }

        // ---- softmax denominators ----
        #pragma unroll
        for (int mt = 0; mt < 2; mt++) {
            #pragma unroll
            for (int j = 0; j < 2; j++) {
                float v = lsum[mt][j];
                v += __shfl_xor_sync(0xffffffffu, v, 1);
                v += __shfl_xor_sync(0xffffffffu, v, 2);
                lsum[mt][j] = v;
            }
        }
        if (t4 == 0) {
            #pragma unroll
            for (int mt = 0; mt < 2; mt++) {
                int rb = rg*32 + mt*16;
                sS[ch*64 + rb + g    ] = lsum[mt][0];
                sS[ch*64 + rb + g + 8] = lsum[mt][1];
            }
        }
        __syncthreads();
        float inv[2][2];
        #pragma unroll
        for (int mt = 0; mt < 2; mt++) {
            int rb = rg*32 + mt*16;
            float d0 = 0.f, d1 = 0.f;
            #pragma unroll
            for (int c = 0; c < 4; c++) {
                d0 += sS[c*64 + rb + g    ];
                d1 += sS[c*64 + rb + g + 8];
            }
            inv[mt][0] = 1.0f / d0;
            inv[mt][1] = 1.0f / d1;
        }

        if (pass == 0) {
            float* st = g_o[h];
            #pragma unroll
            for (int mt = 0; mt < 2; mt++) {
                int r0 = tokbase + row0 + rg*32 + mt*16 + g;
                #pragma unroll
                for (int n = 0; n < 8; n++) {
                    int col = ch*64 + n*8 + 2*t4;
                    *(float2*)&st[ r0     *256 + col] =
                        make_float2(acc[mt][n][0]*inv[mt][0], acc[mt][n][1]*inv[mt][0]);
                    *(float2*)&st[(r0 + 8)*256 + col] =
                        make_float2(acc[mt][n][2]*inv[mt][1], acc[mt][n][3]*inv[mt][1]);
                }
            }
        } else {
            float cf = coefp[0];
            const float* st = g_o[h];
            int ooff = h * 256;
            #pragma unroll
            for (int mt = 0; mt < 2; mt++) {
                int r0 = tokbase + row0 + rg*32 + mt*16 + g;
                #pragma unroll
                for (int n = 0; n < 8; n++) {
                    int col = ch*64 + n*8 + 2*t4;
                    float2 s0 = *(const float2*)&st[ r0     *256 + col];
                    float2 s1 = *(const float2*)&st[(r0 + 8)*256 + col];
                    float2 o0 = make_float2(acc[mt][n][0]*inv[mt][0] + cf*s0.x,
                                            acc[mt][n][1]*inv[mt][0] + cf*s0.y);
                    float2 o1 = make_float2(acc[mt][n][2]*inv[mt][1] + cf*s1.x,
                                            acc[mt][n][3]*inv[mt][1] + cf*s1.y);
                    *(float2*)&dst[ r0     *512 + ooff + col] = o0;
                    *(float2*)&dst[(r0 + 8)*512 + ooff + col] = o1;
                }
            }
        }
    }
}

extern "C" void kernel_launch(void* const* d_in, const int* in_sizes, int n_in,
                              void* d_out, int out_size) {
    const float* x = (const float*)d_in[0];
    const float* wt[12];
    for (int i = 0; i < 12; i++) wt[i] = (const float*)d_in[1+i];
    const float* alpha = (const float*)d_in[13];
    const float* gamma = (const float*)d_in[14];
    float* out = (float*)d_out;

    cudaFuncSetAttribute(proj_qk,
                         cudaFuncAttributeMaxDynamicSharedMemorySize, PROJ_SMEM);
    cudaFuncSetAttribute(proj_v,
                         cudaFuncAttributeMaxDynamicSharedMemorySize, PROJ_SMEM);
    cudaFuncSetAttribute(attn_mma,
                         cudaFuncAttributeMaxDynamicSharedMemorySize, ATTN_SMEM);

    split_kernel<<<2048, 256>>>((const float2*)x, NTOK*C_);

    // y0: X=ecg  wa=w1->q0   wb=w2->k0
    // y1: X=ecg  wa=w4->q1   wb=w11->k3
    // y2: X=pcg  wa=w7->q2   wb=w5->k1
    // y3: X=pcg  wa=w8->k2   wb=w10->q3
    QKArgs qk;
    qk.wa[0] = wt[0];  qk.wb[0] = wt[1];
    qk.wa[1] = wt[3];  qk.wb[1] = wt[10];
    qk.wa[2] = wt[6];  qk.wb[2] = wt[4];
    qk.wa[3] = wt[7];  qk.wb[3] = wt[9];
    proj_qk<<<dim3(NTOK/128, 4), 256, PROJ_SMEM>>>(qk);

    VArgs va;
    va.wv[0] = wt[2]; va.wv[1] = wt[5]; va.wv[2] = wt[8]; va.wv[3] = wt[11];
    proj_v<<<dim3(NTOK/128, 4, 4), 256, PROJ_SMEM>>>(va);

    dim3 ag(L_/ROWS, B_, 2);
    attn_mma<<<ag, 256, ATTN_SMEM>>>(out, alpha, gamma);
}